// round 15
// baseline (speedup 1.0000x reference)
#include <cuda_runtime.h>
#include <math.h>

#define N_NODES 20000
#define N_EDGES 320000
#define D 128
#define H 8
#define G 64
#define LN_EPS 1e-5f
#define WMAXD 64

#define WIDTH   (5.0f / 63.0f)
#define INV_W   (63.0f / 5.0f)
#define EXP_COEF (-0.5f * INV_W * INV_W)
#define PI_OVER_CUT 0.62831853071795864f
#define INV_SQRT_P 0.25f

// ---------------- scratch ----------------
static __device__ __align__(16) float g_q[(size_t)N_EDGES * D];     // SORTED by src
static __device__ float g_C[N_EDGES];                               // SORTED by src
static __device__ __align__(16) float g_gk[(size_t)N_NODES * H * D];
static __device__ __align__(16) float g_h2[(size_t)N_NODES * D];
static __device__ int g_hist[N_NODES];
static __device__ int g_off[N_NODES + 1];
static __device__ int g_cursor[N_NODES];
static __device__ int g_pos[N_EDGES];

// ---------------- KH: histogram of src ----------------
__global__ void kh_hist(const int* __restrict__ src) {
    for (int e = blockIdx.x * blockDim.x + threadIdx.x; e < N_EDGES;
         e += gridDim.x * blockDim.x)
        atomicAdd(&g_hist[src[e]], 1);
}

// ---------------- K2: single-block scan; re-zeroes hist ----------------
__global__ void k2_scan() {
    __shared__ int sh[256];
    const int tid = threadIdx.x;
    const int CH = (N_NODES + 255) / 256;
    const int lo = tid * CH;
    const int hi = min(lo + CH, N_NODES);
    int s = 0;
    for (int i = lo; i < hi; i++) s += g_hist[i];
    sh[tid] = s;
    __syncthreads();
    for (int off = 1; off < 256; off <<= 1) {
        int v = (tid >= off) ? sh[tid - off] : 0;
        __syncthreads();
        sh[tid] += v;
        __syncthreads();
    }
    int base = (tid == 0) ? 0 : sh[tid - 1];
    for (int i = lo; i < hi; i++) {
        int c = g_hist[i];
        g_off[i] = base;
        g_cursor[i] = base;
        g_hist[i] = 0;
        base += c;
    }
    if (tid == 0) g_off[N_NODES] = N_EDGES;
}

// ---------------- K1: warp-per-edge; colsum folded; 3-shfl scalar broadcast ----------------
__global__ void __launch_bounds__(256) k1_edge(
    const float* __restrict__ pos, const float* __restrict__ h1,
    const float* __restrict__ t,   const float* __restrict__ fw,
    const float* __restrict__ fb,  const float* __restrict__ ln_g,
    const float* __restrict__ ln_b,const int* __restrict__ src,
    const int* __restrict__ dst,   float* __restrict__ outW)
{
    __shared__ float4 sh_fw[G * 32];
    const int tid  = threadIdx.x;
    const int lane = tid & 31;
    const int w    = tid >> 5;               // 0..7
    const unsigned FULL = 0xffffffffu;

    for (int i = tid; i < G * 32; i += 256) sh_fw[i] = ((const float4*)fw)[i];
    __syncthreads();

    // fbc = fb - colsum (folded once; colsum regs freed)
    float4 fbc4;
    {
        float4 cs = make_float4(0.f, 0.f, 0.f, 0.f);
        #pragma unroll
        for (int g = 0; g < G; g++) {
            const float4 w4 = sh_fw[g * 32 + lane];
            cs.x += w4.x; cs.y += w4.y; cs.z += w4.z; cs.w += w4.w;
        }
        const float4 fb4 = ((const float4*)fb)[lane];
        fbc4.x = fb4.x - cs.x; fbc4.y = fb4.y - cs.y;
        fbc4.z = fb4.z - cs.z; fbc4.w = fb4.w - cs.w;
    }
    const float4 lg4 = ((const float4*)ln_g)[lane];
    const float4 lb4 = ((const float4*)ln_b)[lane];

    const int e0 = blockIdx.x * 128 + w * 16;

    // ---- scalar phase: lanes 0..15 handle one edge each ----
    int dn_me = 0, p_me = 0;
    float r_me = 0.f, C_me = 0.f;
    if (lane < 16) {
        const int e = e0 + lane;
        const int s = src[e];
        dn_me = dst[e];
        const float dx = pos[dn_me*3+0] - pos[s*3+0];
        const float dy = pos[dn_me*3+1] - pos[s*3+1];
        const float dz = pos[dn_me*3+2] - pos[s*3+2];
        r_me = sqrtf(dx*dx + dy*dy + dz*dz);
        C_me = (r_me < 5.0f) ? 0.5f * (__cosf(r_me * PI_OVER_CUT) + 1.0f) : 0.0f;
        p_me = atomicAdd(&g_cursor[s], 1);
        g_pos[e] = p_me;
        g_C[p_me] = C_me;
    }

    // prefetch edge 0's h1/t rows
    int dn_nx = __shfl_sync(FULL, dn_me, 0);
    float4 h4n = ((const float4*)h1)[(size_t)dn_nx * 32 + lane];
    float4 t4n = ((const float4*)t)[(size_t)e0 * 32 + lane];

    #pragma unroll 1
    for (int ei = 0; ei < 16; ei++) {
        const int e = e0 + ei;
        const float4 h4 = h4n;
        const float4 t4 = t4n;
        if (ei + 1 < 16) {
            dn_nx = __shfl_sync(FULL, dn_me, ei + 1);
            h4n = ((const float4*)h1)[(size_t)dn_nx * 32 + lane];
            t4n = ((const float4*)t)[(size_t)(e + 1) * 32 + lane];
        }
        const int   p_e = __shfl_sync(FULL, p_me, ei);
        const float C_e = __shfl_sync(FULL, C_me, ei);
        const float r_e = __shfl_sync(FULL, r_me, ei);
        // recompute window per-lane (ALU cheaper than 2 extra shfls)
        const int i0_e  = __float2int_rn(r_e * INV_W);
        const int glo_e = max(0, i0_e - 4);
        const int ghi_e = min(G - 1, i0_e + 4);
        const int nwin_e = ghi_e - glo_e + 1;     // <= 9

        float myf = 0.f;
        if (lane < nwin_e) {
            const float dr = r_e - (glo_e + lane) * WIDTH;
            myf = __expf(EXP_COEF * dr * dr);
        }

        float4 acc = make_float4(0.f, 0.f, 0.f, 0.f);
        for (int j = 0; j < nwin_e; j++) {
            const float fj = __shfl_sync(FULL, myf, j);
            const float4 w4 = sh_fw[(glo_e + j) * 32 + lane];
            acc.x += fj * w4.x; acc.y += fj * w4.y;
            acc.z += fj * w4.z; acc.w += fj * w4.w;
        }
        float4 W4;
        W4.x = (2.0f * acc.x + fbc4.x) * C_e;
        W4.y = (2.0f * acc.y + fbc4.y) * C_e;
        W4.z = (2.0f * acc.z + fbc4.z) * C_e;
        W4.w = (2.0f * acc.w + fbc4.w) * C_e;
        ((float4*)outW)[(size_t)e * 32 + lane] = W4;

        float4 v;
        v.x = W4.x * h4.x + t4.x; v.y = W4.y * h4.y + t4.y;
        v.z = W4.z * h4.z + t4.z; v.w = W4.w * h4.w + t4.w;

        float sm = v.x + v.y + v.z + v.w;
        float sq = v.x*v.x + v.y*v.y + v.z*v.z + v.w*v.w;
        #pragma unroll
        for (int o = 16; o; o >>= 1) {
            sm += __shfl_xor_sync(FULL, sm, o);
            sq += __shfl_xor_sync(FULL, sq, o);
        }
        const float mu  = sm * (1.0f / D);
        const float var = sq * (1.0f / D) - mu * mu;
        const float inv = rsqrtf(var + LN_EPS);
        float4 qo;
        qo.x = (v.x - mu) * inv * lg4.x + lb4.x;
        qo.y = (v.y - mu) * inv * lg4.y + lb4.y;
        qo.z = (v.z - mu) * inv * lg4.z + lb4.z;
        qo.w = (v.w - mu) * inv * lg4.w + lb4.w;
        ((float4*)g_q)[(size_t)p_e * 32 + lane] = qo;
    }
}

// ---------------- K45: 512 threads, 64-node tiles; qv smem-resident then gk ----------------
__global__ void __launch_bounds__(512) k45_gk(
    const float* __restrict__ Wq, const float* __restrict__ Wk,
    const int* __restrict__ q_id)
{
    extern __shared__ float sm[];
    float* shWq  = sm;                    // 16384
    float* shWkT = shWq + 16384;          // 128*132 = 16896
    float* shq   = shWkT + 16896;         // 64*128 = 8192
    float* shqv  = shq + 8192;            // 8192
    int*   shIdx = (int*)(shqv + 8192);   // 64
    const int tid = threadIdx.x;
    const int tx = tid & 31, ty = tid >> 5;      // ty 0..15

    for (int i = tid; i < D * D; i += 512) shWq[i] = Wq[i];
    for (int i = tid; i < D * D; i += 512) {
        const int d = i >> 7, j = i & 127;
        shWkT[j * 132 + d] = Wk[i];
    }
    const float4* wrow = (const float4*)shWkT;   // row stride 33 float4

    const int NT = (N_NODES + 63) / 64;          // 313
    for (int tile = blockIdx.x; tile < NT; tile += gridDim.x) {
        const int n0 = tile * 64;
        __syncthreads();
        if (tid < 64) {
            const int nn = n0 + tid;
            shIdx[tid] = g_pos[q_id[(nn < N_NODES) ? nn : 0]];
        }
        __syncthreads();
        for (int i = tid; i < 2048; i += 512)
            ((float4*)shq)[i] = ((const float4*)g_q)[(size_t)shIdx[i >> 5] * 32 + (i & 31)];
        __syncthreads();

        {   // qv = shq @ Wq
            float4 a0 = make_float4(0,0,0,0), a1 = a0, a2 = a0, a3 = a0;
            const float* q0 = shq + (ty * 4) * D;
            #pragma unroll 4
            for (int k = 0; k < D; k++) {
                const float4 wv = ((const float4*)shWq)[k * 32 + tx];
                const float b0 = q0[k], b1 = q0[D + k], b2 = q0[2*D + k], b3 = q0[3*D + k];
                a0.x += b0*wv.x; a0.y += b0*wv.y; a0.z += b0*wv.z; a0.w += b0*wv.w;
                a1.x += b1*wv.x; a1.y += b1*wv.y; a1.z += b1*wv.z; a1.w += b1*wv.w;
                a2.x += b2*wv.x; a2.y += b2*wv.y; a2.z += b2*wv.z; a2.w += b2*wv.w;
                a3.x += b3*wv.x; a3.y += b3*wv.y; a3.z += b3*wv.z; a3.w += b3*wv.w;
            }
            ((float4*)shqv)[(ty*4 + 0) * 32 + tx] = a0;
            ((float4*)shqv)[(ty*4 + 1) * 32 + tx] = a1;
            ((float4*)shqv)[(ty*4 + 2) * 32 + tx] = a2;
            ((float4*)shqv)[(ty*4 + 3) * 32 + tx] = a3;
        }
        __syncthreads();

        {   // gk[n,h,:] : warp ty -> head (ty&7), node-half (ty>>3)
            const int h = ty & 7, half = ty >> 3, c = tx;
            #pragma unroll 1
            for (int n = 0; n < 32; n++) {
                const int nn = half * 32 + n;
                const float* qn = shqv + nn * D + h * 16;
                float4 acc = make_float4(0,0,0,0);
                #pragma unroll
                for (int p = 0; p < 16; p++) {
                    const float a = qn[p];
                    const float4 w4 = wrow[(h*16 + p) * 33 + c];
                    acc.x += a*w4.x; acc.y += a*w4.y; acc.z += a*w4.z; acc.w += a*w4.w;
                }
                if (n0 + nn < N_NODES)
                    ((float4*)g_gk)[((size_t)(n0 + nn) * H + h) * 32 + c] = acc;
            }
        }
    }
}

// ---------------- K7: WARP-PER-NODE, single-pass; 192 threads => 170-reg cap ----------------
__global__ void __launch_bounds__(192, 2) k7_node(const float* __restrict__ Wv) {
    extern __shared__ float sm[];
    float* shWv  = sm;                  // 16384 (64 KB)
    float* shBuf = shWv + 16384;        // 6 * 1024  per-warp Y staging
    float* shCb  = shBuf + 6144;        // 6 * 64    per-warp C

    const int tid  = threadIdx.x;
    const int lane = tid & 31;
    const int w    = tid >> 5;          // 0..5
    const unsigned FULL = 0xffffffffu;
    float* myL = shBuf + w * 1024;
    float* myC = shCb + w * WMAXD;

    for (int i = tid; i < D * D; i += 192) shWv[i] = Wv[i];
    __syncthreads();

    for (int n = blockIdx.x * 6 + w; n < N_NODES; n += gridDim.x * 6) {
        const int base = g_off[n];
        const int deg  = g_off[n + 1] - base;
        if (deg == 0) {
            ((float4*)g_h2)[(size_t)n * 32 + lane] = make_float4(0,0,0,0);
            continue;
        }

        float4 g4[H];
        #pragma unroll
        for (int h = 0; h < H; h++)
            g4[h] = ((const float4*)g_gk)[((size_t)n * H + h) * 32 + lane];

        float4 Y[H];
        #pragma unroll
        for (int h = 0; h < H; h++) Y[h] = make_float4(0,0,0,0);

        if (deg <= WMAXD) {
            for (int j = lane; j < deg; j += 32) myC[j] = g_C[base + j];
            __syncwarp();

            float s_own = 0.f;
            float4 qn = ((const float4*)g_q)[(size_t)base * 32 + lane];
            for (int i = 0; i < deg; i++) {
                const float4 q4 = qn;
                const float Ce = myC[i];
                if (i + 1 < deg)
                    qn = ((const float4*)g_q)[(size_t)(base + i + 1) * 32 + lane];
                float pr0 = q4.x*g4[0].x + q4.y*g4[0].y + q4.z*g4[0].z + q4.w*g4[0].w;
                float pr1 = q4.x*g4[1].x + q4.y*g4[1].y + q4.z*g4[1].z + q4.w*g4[1].w;
                float pr2 = q4.x*g4[2].x + q4.y*g4[2].y + q4.z*g4[2].z + q4.w*g4[2].w;
                float pr3 = q4.x*g4[3].x + q4.y*g4[3].y + q4.z*g4[3].z + q4.w*g4[3].w;
                float pr4 = q4.x*g4[4].x + q4.y*g4[4].y + q4.z*g4[4].z + q4.w*g4[4].w;
                float pr5 = q4.x*g4[5].x + q4.y*g4[5].y + q4.z*g4[5].z + q4.w*g4[5].w;
                float pr6 = q4.x*g4[6].x + q4.y*g4[6].y + q4.z*g4[6].z + q4.w*g4[6].w;
                float pr7 = q4.x*g4[7].x + q4.y*g4[7].y + q4.z*g4[7].z + q4.w*g4[7].w;
                #pragma unroll
                for (int off = 16; off >= 4; off >>= 1) {
                    pr0 += __shfl_xor_sync(FULL, pr0, off);
                    pr1 += __shfl_xor_sync(FULL, pr1, off);
                    pr2 += __shfl_xor_sync(FULL, pr2, off);
                    pr3 += __shfl_xor_sync(FULL, pr3, off);
                    pr4 += __shfl_xor_sync(FULL, pr4, off);
                    pr5 += __shfl_xor_sync(FULL, pr5, off);
                    pr6 += __shfl_xor_sync(FULL, pr6, off);
                    pr7 += __shfl_xor_sync(FULL, pr7, off);
                }
                const float t0 = (lane & 4) ? pr1 : pr0;
                const float t1 = (lane & 4) ? pr3 : pr2;
                const float t2 = (lane & 4) ? pr5 : pr4;
                const float t3 = (lane & 4) ? pr7 : pr6;
                const float u0 = (lane & 8) ? t1 : t0;
                const float u1 = (lane & 8) ? t3 : t2;
                float x = (lane & 16) ? u1 : u0;
                x += __shfl_xor_sync(FULL, x, 2);
                x += __shfl_xor_sync(FULL, x, 1);
                const float a = __expf(x * INV_SQRT_P) * Ce;
                s_own += a;
                const float a0 = __shfl_sync(FULL, a, 0);
                const float a1 = __shfl_sync(FULL, a, 4);
                const float a2 = __shfl_sync(FULL, a, 8);
                const float a3 = __shfl_sync(FULL, a, 12);
                const float a4 = __shfl_sync(FULL, a, 16);
                const float a5 = __shfl_sync(FULL, a, 20);
                const float a6 = __shfl_sync(FULL, a, 24);
                const float a7 = __shfl_sync(FULL, a, 28);
                Y[0].x += a0*q4.x; Y[0].y += a0*q4.y; Y[0].z += a0*q4.z; Y[0].w += a0*q4.w;
                Y[1].x += a1*q4.x; Y[1].y += a1*q4.y; Y[1].z += a1*q4.z; Y[1].w += a1*q4.w;
                Y[2].x += a2*q4.x; Y[2].y += a2*q4.y; Y[2].z += a2*q4.z; Y[2].w += a2*q4.w;
                Y[3].x += a3*q4.x; Y[3].y += a3*q4.y; Y[3].z += a3*q4.z; Y[3].w += a3*q4.w;
                Y[4].x += a4*q4.x; Y[4].y += a4*q4.y; Y[4].z += a4*q4.z; Y[4].w += a4*q4.w;
                Y[5].x += a5*q4.x; Y[5].y += a5*q4.y; Y[5].z += a5*q4.z; Y[5].w += a5*q4.w;
                Y[6].x += a6*q4.x; Y[6].y += a6*q4.y; Y[6].z += a6*q4.z; Y[6].w += a6*q4.w;
                Y[7].x += a7*q4.x; Y[7].y += a7*q4.y; Y[7].z += a7*q4.z; Y[7].w += a7*q4.w;
            }
            #pragma unroll
            for (int h = 0; h < H; h++) {
                const float sh_ = __shfl_sync(FULL, s_own, h << 2);
                const float si = 1.0f / sh_;
                Y[h].x *= si; Y[h].y *= si; Y[h].z *= si; Y[h].w *= si;
                *(float4*)&myL[h * D + lane * 4] = Y[h];
            }
            __syncwarp();
        } else {
            float m[H], s[H];
            #pragma unroll
            for (int h = 0; h < H; h++) { m[h] = -1e30f; s[h] = 0.f; }
            for (int i = 0; i < deg; i++) {
                const float4 q4 = ((const float4*)g_q)[(size_t)(base + i) * 32 + lane];
                const float Ce = g_C[base + i];
                #pragma unroll
                for (int h = 0; h < H; h++) {
                    float pq = q4.x*g4[h].x + q4.y*g4[h].y + q4.z*g4[h].z + q4.w*g4[h].w;
                    #pragma unroll
                    for (int o = 16; o; o >>= 1) pq += __shfl_xor_sync(FULL, pq, o);
                    pq *= INV_SQRT_P;
                    const float nm = fmaxf(m[h], pq);
                    const float sc = __expf(m[h] - nm);
                    const float ww = __expf(pq - nm) * Ce;
                    s[h] = s[h] * sc + ww;
                    Y[h].x = Y[h].x * sc + ww * q4.x;
                    Y[h].y = Y[h].y * sc + ww * q4.y;
                    Y[h].z = Y[h].z * sc + ww * q4.z;
                    Y[h].w = Y[h].w * sc + ww * q4.w;
                    m[h] = nm;
                }
            }
            #pragma unroll
            for (int h = 0; h < H; h++) {
                const float si = 1.0f / s[h];
                Y[h].x *= si; Y[h].y *= si; Y[h].z *= si; Y[h].w *= si;
                *(float4*)&myL[h * D + lane * 4] = Y[h];
            }
            __syncwarp();
        }

        // ---- epilogue: h2[j] = sum_d Y[j>>4, d] * Wv[d, j] ----
        const float* yrow = myL + (lane >> 2) * D;
        float4 hv = make_float4(0,0,0,0);
        #pragma unroll 8
        for (int d = 0; d < D; d += 4) {
            const float4 y4 = *(const float4*)&yrow[d];
            const float4 w0 = ((const float4*)shWv)[(d+0) * 32 + lane];
            const float4 w1 = ((const float4*)shWv)[(d+1) * 32 + lane];
            const float4 w2 = ((const float4*)shWv)[(d+2) * 32 + lane];
            const float4 w3 = ((const float4*)shWv)[(d+3) * 32 + lane];
            hv.x += y4.x*w0.x + y4.y*w1.x + y4.z*w2.x + y4.w*w3.x;
            hv.y += y4.x*w0.y + y4.y*w1.y + y4.z*w2.y + y4.w*w3.y;
            hv.z += y4.x*w0.z + y4.y*w1.z + y4.z*w2.z + y4.w*w3.z;
            hv.w += y4.x*w0.w + y4.y*w1.w + y4.z*w2.w + y4.w*w3.w;
        }
        ((float4*)g_h2)[(size_t)n * 32 + lane] = hv;
    }
}

// ---------------- K8: tiled m_agg = h2 @ Wo ----------------
__global__ void __launch_bounds__(256) k8_out(const float* __restrict__ Wo,
                                              float* __restrict__ outM) {
    extern __shared__ float sm[];
    float* shW = sm;             // 16384
    float* shq = shW + 16384;    // 4096
    const int tid = threadIdx.x;
    const int tx = tid & 31, ty = tid >> 5;

    for (int i = tid; i < D * D; i += 256) shW[i] = Wo[i];

    for (int tile = blockIdx.x; tile < N_NODES / 32; tile += gridDim.x) {
        const int n0 = tile * 32;
        __syncthreads();
        for (int i = tid; i < 1024; i += 256)
            ((float4*)shq)[i] = ((const float4*)g_h2)[(size_t)n0 * 32 + i];
        __syncthreads();

        float4 a0 = make_float4(0,0,0,0), a1 = a0, a2 = a0, a3 = a0;
        const float* q0 = shq + (ty * 4) * D;
        #pragma unroll 4
        for (int k = 0; k < D; k++) {
            const float4 wv = ((const float4*)shW)[k * 32 + tx];
            const float b0 = q0[k], b1 = q0[D + k], b2 = q0[2*D + k], b3 = q0[3*D + k];
            a0.x += b0*wv.x; a0.y += b0*wv.y; a0.z += b0*wv.z; a0.w += b0*wv.w;
            a1.x += b1*wv.x; a1.y += b1*wv.y; a1.z += b1*wv.z; a1.w += b1*wv.w;
            a2.x += b2*wv.x; a2.y += b2*wv.y; a2.z += b2*wv.z; a2.w += b2*wv.w;
            a3.x += b3*wv.x; a3.y += b3*wv.y; a3.z += b3*wv.z; a3.w += b3*wv.w;
        }
        ((float4*)outM)[(size_t)(n0 + ty*4 + 0) * 32 + tx] = a0;
        ((float4*)outM)[(size_t)(n0 + ty*4 + 1) * 32 + tx] = a1;
        ((float4*)outM)[(size_t)(n0 + ty*4 + 2) * 32 + tx] = a2;
        ((float4*)outM)[(size_t)(n0 + ty*4 + 3) * 32 + tx] = a3;
    }
}

// ---------------- launch ----------------
extern "C" void kernel_launch(void* const* d_in, const int* in_sizes, int n_in,
                              void* d_out, int out_size) {
    const float* pos  = (const float*)d_in[0];
    const float* h1   = (const float*)d_in[1];
    const float* t    = (const float*)d_in[2];
    const float* fw   = (const float*)d_in[3];
    const float* fb   = (const float*)d_in[4];
    const float* ln_g = (const float*)d_in[5];
    const float* ln_b = (const float*)d_in[6];
    const float* Wq   = (const float*)d_in[7];
    const float* Wk   = (const float*)d_in[8];
    const float* Wv   = (const float*)d_in[9];
    const float* Wo   = (const float*)d_in[10];
    const int* src    = (const int*)d_in[11];
    const int* dst    = (const int*)d_in[12];
    const int* q_id   = (const int*)d_in[13];

    float* out  = (float*)d_out;
    float* outM = out;                              // m_agg [N,D]
    float* outW = out + (size_t)N_NODES * D;        // W     [E,D]

    const size_t sm_k45 = (16384 + 16896 + 8192 + 8192) * sizeof(float) + 64 * sizeof(int);
    const size_t sm_k7  = (16384 + 6144 + 384) * sizeof(float);      // 91,648 B (x2 CTAs = 179KB)
    const size_t sm_k8  = (16384 + 4096) * sizeof(float);

    cudaFuncSetAttribute(k45_gk,  cudaFuncAttributeMaxDynamicSharedMemorySize, (int)sm_k45);
    cudaFuncSetAttribute(k7_node, cudaFuncAttributeMaxDynamicSharedMemorySize, (int)sm_k7);
    cudaFuncSetAttribute(k8_out,  cudaFuncAttributeMaxDynamicSharedMemorySize, (int)sm_k8);

    kh_hist<<<256, 256>>>(src);                                       // 0
    k2_scan<<<1, 256>>>();                                            // 1
    k1_edge<<<N_EDGES / 128, 256>>>(pos, h1, t, fw, fb, ln_g, ln_b,
                                    src, dst, outW);                  // 2
    k45_gk<<<148, 512, sm_k45>>>(Wq, Wk, q_id);                       // 3  <-- profiled
    k7_node<<<296, 192, sm_k7>>>(Wv);                                 // 4
    k8_out<<<296, 256, sm_k8>>>(Wo, outM);                            // 5
}

// round 16
// speedup vs baseline: 1.0626x; 1.0626x over previous
#include <cuda_runtime.h>
#include <math.h>

#define N_NODES 20000
#define N_EDGES 320000
#define D 128
#define H 8
#define G 64
#define LN_EPS 1e-5f
#define WMAXD 64

#define WIDTH   (5.0f / 63.0f)
#define INV_W   (63.0f / 5.0f)
#define EXP_COEF (-0.5f * INV_W * INV_W)
#define PI_OVER_CUT 0.62831853071795864f
#define INV_SQRT_P 0.25f

// ---------------- scratch ----------------
static __device__ __align__(16) float g_q[(size_t)N_EDGES * D];     // SORTED by src
static __device__ float g_C[N_EDGES];                               // SORTED by src
static __device__ __align__(16) float g_gk[(size_t)N_NODES * H * D];
static __device__ __align__(16) float g_h2[(size_t)N_NODES * D];
static __device__ int g_hist[N_NODES];
static __device__ int g_off[N_NODES + 1];
static __device__ int g_cursor[N_NODES];
static __device__ int g_pos[N_EDGES];

// ---------------- KH: histogram of src ----------------
__global__ void kh_hist(const int* __restrict__ src) {
    for (int e = blockIdx.x * blockDim.x + threadIdx.x; e < N_EDGES;
         e += gridDim.x * blockDim.x)
        atomicAdd(&g_hist[src[e]], 1);
}

// ---------------- K2: single-block scan; re-zeroes hist ----------------
__global__ void k2_scan() {
    __shared__ int sh[256];
    const int tid = threadIdx.x;
    const int CH = (N_NODES + 255) / 256;
    const int lo = tid * CH;
    const int hi = min(lo + CH, N_NODES);
    int s = 0;
    for (int i = lo; i < hi; i++) s += g_hist[i];
    sh[tid] = s;
    __syncthreads();
    for (int off = 1; off < 256; off <<= 1) {
        int v = (tid >= off) ? sh[tid - off] : 0;
        __syncthreads();
        sh[tid] += v;
        __syncthreads();
    }
    int base = (tid == 0) ? 0 : sh[tid - 1];
    for (int i = lo; i < hi; i++) {
        int c = g_hist[i];
        g_off[i] = base;
        g_cursor[i] = base;
        g_hist[i] = 0;
        base += c;
    }
    if (tid == 0) g_off[N_NODES] = N_EDGES;
}

// ---------------- K1: warp-per-edge; colsum folded; 3-shfl scalar broadcast ----------------
__global__ void __launch_bounds__(256) k1_edge(
    const float* __restrict__ pos, const float* __restrict__ h1,
    const float* __restrict__ t,   const float* __restrict__ fw,
    const float* __restrict__ fb,  const float* __restrict__ ln_g,
    const float* __restrict__ ln_b,const int* __restrict__ src,
    const int* __restrict__ dst,   float* __restrict__ outW)
{
    __shared__ float4 sh_fw[G * 32];
    const int tid  = threadIdx.x;
    const int lane = tid & 31;
    const int w    = tid >> 5;               // 0..7
    const unsigned FULL = 0xffffffffu;

    for (int i = tid; i < G * 32; i += 256) sh_fw[i] = ((const float4*)fw)[i];
    __syncthreads();

    float4 fbc4;
    {
        float4 cs = make_float4(0.f, 0.f, 0.f, 0.f);
        #pragma unroll
        for (int g = 0; g < G; g++) {
            const float4 w4 = sh_fw[g * 32 + lane];
            cs.x += w4.x; cs.y += w4.y; cs.z += w4.z; cs.w += w4.w;
        }
        const float4 fb4 = ((const float4*)fb)[lane];
        fbc4.x = fb4.x - cs.x; fbc4.y = fb4.y - cs.y;
        fbc4.z = fb4.z - cs.z; fbc4.w = fb4.w - cs.w;
    }
    const float4 lg4 = ((const float4*)ln_g)[lane];
    const float4 lb4 = ((const float4*)ln_b)[lane];

    const int e0 = blockIdx.x * 128 + w * 16;

    // ---- scalar phase: lanes 0..15 handle one edge each ----
    int dn_me = 0, p_me = 0;
    float r_me = 0.f, C_me = 0.f;
    if (lane < 16) {
        const int e = e0 + lane;
        const int s = src[e];
        dn_me = dst[e];
        const float dx = pos[dn_me*3+0] - pos[s*3+0];
        const float dy = pos[dn_me*3+1] - pos[s*3+1];
        const float dz = pos[dn_me*3+2] - pos[s*3+2];
        r_me = sqrtf(dx*dx + dy*dy + dz*dz);
        C_me = (r_me < 5.0f) ? 0.5f * (__cosf(r_me * PI_OVER_CUT) + 1.0f) : 0.0f;
        p_me = atomicAdd(&g_cursor[s], 1);
        g_pos[e] = p_me;
        g_C[p_me] = C_me;
    }

    int dn_nx = __shfl_sync(FULL, dn_me, 0);
    float4 h4n = ((const float4*)h1)[(size_t)dn_nx * 32 + lane];
    float4 t4n = ((const float4*)t)[(size_t)e0 * 32 + lane];

    #pragma unroll 1
    for (int ei = 0; ei < 16; ei++) {
        const int e = e0 + ei;
        const float4 h4 = h4n;
        const float4 t4 = t4n;
        if (ei + 1 < 16) {
            dn_nx = __shfl_sync(FULL, dn_me, ei + 1);
            h4n = ((const float4*)h1)[(size_t)dn_nx * 32 + lane];
            t4n = ((const float4*)t)[(size_t)(e + 1) * 32 + lane];
        }
        const int   p_e = __shfl_sync(FULL, p_me, ei);
        const float C_e = __shfl_sync(FULL, C_me, ei);
        const float r_e = __shfl_sync(FULL, r_me, ei);
        const int i0_e  = __float2int_rn(r_e * INV_W);
        const int glo_e = max(0, i0_e - 4);
        const int ghi_e = min(G - 1, i0_e + 4);
        const int nwin_e = ghi_e - glo_e + 1;     // <= 9

        float myf = 0.f;
        if (lane < nwin_e) {
            const float dr = r_e - (glo_e + lane) * WIDTH;
            myf = __expf(EXP_COEF * dr * dr);
        }

        float4 acc = make_float4(0.f, 0.f, 0.f, 0.f);
        for (int j = 0; j < nwin_e; j++) {
            const float fj = __shfl_sync(FULL, myf, j);
            const float4 w4 = sh_fw[(glo_e + j) * 32 + lane];
            acc.x += fj * w4.x; acc.y += fj * w4.y;
            acc.z += fj * w4.z; acc.w += fj * w4.w;
        }
        float4 W4;
        W4.x = (2.0f * acc.x + fbc4.x) * C_e;
        W4.y = (2.0f * acc.y + fbc4.y) * C_e;
        W4.z = (2.0f * acc.z + fbc4.z) * C_e;
        W4.w = (2.0f * acc.w + fbc4.w) * C_e;
        ((float4*)outW)[(size_t)e * 32 + lane] = W4;

        float4 v;
        v.x = W4.x * h4.x + t4.x; v.y = W4.y * h4.y + t4.y;
        v.z = W4.z * h4.z + t4.z; v.w = W4.w * h4.w + t4.w;

        float sm = v.x + v.y + v.z + v.w;
        float sq = v.x*v.x + v.y*v.y + v.z*v.z + v.w*v.w;
        #pragma unroll
        for (int o = 16; o; o >>= 1) {
            sm += __shfl_xor_sync(FULL, sm, o);
            sq += __shfl_xor_sync(FULL, sq, o);
        }
        const float mu  = sm * (1.0f / D);
        const float var = sq * (1.0f / D) - mu * mu;
        const float inv = rsqrtf(var + LN_EPS);
        float4 qo;
        qo.x = (v.x - mu) * inv * lg4.x + lb4.x;
        qo.y = (v.y - mu) * inv * lg4.y + lb4.y;
        qo.z = (v.z - mu) * inv * lg4.z + lb4.z;
        qo.w = (v.w - mu) * inv * lg4.w + lb4.w;
        ((float4*)g_q)[(size_t)p_e * 32 + lane] = qo;
    }
}

// ---------------- K45: 512 threads, 64-node tiles; gk phase 4-node register-blocked ----------------
__global__ void __launch_bounds__(512) k45_gk(
    const float* __restrict__ Wq, const float* __restrict__ Wk,
    const int* __restrict__ q_id)
{
    extern __shared__ float sm[];
    float* shWq  = sm;                    // 16384
    float* shWkT = shWq + 16384;          // 128*132 = 16896
    float* shq   = shWkT + 16896;         // 64*128 = 8192
    float* shqv  = shq + 8192;            // 8192
    int*   shIdx = (int*)(shqv + 8192);   // 64
    const int tid = threadIdx.x;
    const int tx = tid & 31, ty = tid >> 5;      // ty 0..15

    for (int i = tid; i < D * D; i += 512) shWq[i] = Wq[i];
    for (int i = tid; i < D * D; i += 512) {
        const int d = i >> 7, j = i & 127;
        shWkT[j * 132 + d] = Wk[i];
    }
    const float4* wrow = (const float4*)shWkT;   // row stride 33 float4

    const int NT = (N_NODES + 63) / 64;          // 313
    for (int tile = blockIdx.x; tile < NT; tile += gridDim.x) {
        const int n0 = tile * 64;
        __syncthreads();
        if (tid < 64) {
            const int nn = n0 + tid;
            shIdx[tid] = g_pos[q_id[(nn < N_NODES) ? nn : 0]];
        }
        __syncthreads();
        for (int i = tid; i < 2048; i += 512)
            ((float4*)shq)[i] = ((const float4*)g_q)[(size_t)shIdx[i >> 5] * 32 + (i & 31)];
        __syncthreads();

        {   // qv = shq @ Wq
            float4 a0 = make_float4(0,0,0,0), a1 = a0, a2 = a0, a3 = a0;
            const float* q0 = shq + (ty * 4) * D;
            #pragma unroll 4
            for (int k = 0; k < D; k++) {
                const float4 wv = ((const float4*)shWq)[k * 32 + tx];
                const float b0 = q0[k], b1 = q0[D + k], b2 = q0[2*D + k], b3 = q0[3*D + k];
                a0.x += b0*wv.x; a0.y += b0*wv.y; a0.z += b0*wv.z; a0.w += b0*wv.w;
                a1.x += b1*wv.x; a1.y += b1*wv.y; a1.z += b1*wv.z; a1.w += b1*wv.w;
                a2.x += b2*wv.x; a2.y += b2*wv.y; a2.z += b2*wv.z; a2.w += b2*wv.w;
                a3.x += b3*wv.x; a3.y += b3*wv.y; a3.z += b3*wv.z; a3.w += b3*wv.w;
            }
            ((float4*)shqv)[(ty*4 + 0) * 32 + tx] = a0;
            ((float4*)shqv)[(ty*4 + 1) * 32 + tx] = a1;
            ((float4*)shqv)[(ty*4 + 2) * 32 + tx] = a2;
            ((float4*)shqv)[(ty*4 + 3) * 32 + tx] = a3;
        }
        __syncthreads();

        {   // gk phase: warp ty -> head (ty&7), node-half (ty>>3); 4 nodes per pass
            const int h = ty & 7, half = ty >> 3, c = tx;
            const int wbase = h * 16;
            #pragma unroll 1
            for (int n = 0; n < 32; n += 4) {
                const int nn = half * 32 + n;
                const float* q0 = shqv + nn * D + wbase;
                const float* q1 = q0 + D;
                const float* q2 = q0 + 2 * D;
                const float* q3 = q0 + 3 * D;
                float4 c0 = make_float4(0,0,0,0), c1 = c0, c2 = c0, c3 = c0;
                #pragma unroll
                for (int p4 = 0; p4 < 4; p4++) {
                    const float4 a0 = *(const float4*)&q0[p4 * 4];
                    const float4 a1 = *(const float4*)&q1[p4 * 4];
                    const float4 a2 = *(const float4*)&q2[p4 * 4];
                    const float4 a3 = *(const float4*)&q3[p4 * 4];
                    const float4 w0 = wrow[(wbase + p4*4 + 0) * 33 + c];
                    const float4 w1 = wrow[(wbase + p4*4 + 1) * 33 + c];
                    const float4 w2 = wrow[(wbase + p4*4 + 2) * 33 + c];
                    const float4 w3 = wrow[(wbase + p4*4 + 3) * 33 + c];
                    c0.x += a0.x*w0.x + a0.y*w1.x + a0.z*w2.x + a0.w*w3.x;
                    c0.y += a0.x*w0.y + a0.y*w1.y + a0.z*w2.y + a0.w*w3.y;
                    c0.z += a0.x*w0.z + a0.y*w1.z + a0.z*w2.z + a0.w*w3.z;
                    c0.w += a0.x*w0.w + a0.y*w1.w + a0.z*w2.w + a0.w*w3.w;
                    c1.x += a1.x*w0.x + a1.y*w1.x + a1.z*w2.x + a1.w*w3.x;
                    c1.y += a1.x*w0.y + a1.y*w1.y + a1.z*w2.y + a1.w*w3.y;
                    c1.z += a1.x*w0.z + a1.y*w1.z + a1.z*w2.z + a1.w*w3.z;
                    c1.w += a1.x*w0.w + a1.y*w1.w + a1.z*w2.w + a1.w*w3.w;
                    c2.x += a2.x*w0.x + a2.y*w1.x + a2.z*w2.x + a2.w*w3.x;
                    c2.y += a2.x*w0.y + a2.y*w1.y + a2.z*w2.y + a2.w*w3.y;
                    c2.z += a2.x*w0.z + a2.y*w1.z + a2.z*w2.z + a2.w*w3.z;
                    c2.w += a2.x*w0.w + a2.y*w1.w + a2.z*w2.w + a2.w*w3.w;
                    c3.x += a3.x*w0.x + a3.y*w1.x + a3.z*w2.x + a3.w*w3.x;
                    c3.y += a3.x*w0.y + a3.y*w1.y + a3.z*w2.y + a3.w*w3.y;
                    c3.z += a3.x*w0.z + a3.y*w1.z + a3.z*w2.z + a3.w*w3.z;
                    c3.w += a3.x*w0.w + a3.y*w1.w + a3.z*w2.w + a3.w*w3.w;
                }
                const int gn = n0 + nn;
                if (gn + 0 < N_NODES) ((float4*)g_gk)[((size_t)(gn+0) * H + h) * 32 + c] = c0;
                if (gn + 1 < N_NODES) ((float4*)g_gk)[((size_t)(gn+1) * H + h) * 32 + c] = c1;
                if (gn + 2 < N_NODES) ((float4*)g_gk)[((size_t)(gn+2) * H + h) * 32 + c] = c2;
                if (gn + 3 < N_NODES) ((float4*)g_gk)[((size_t)(gn+3) * H + h) * 32 + c] = c3;
            }
        }
    }
}

// ---------------- K7: WARP-PER-NODE, single-pass unshifted softmax (256 thr, 2 CTAs/SM) ----------------
__global__ void __launch_bounds__(256, 2) k7_node(const float* __restrict__ Wv) {
    extern __shared__ float sm[];
    float* shWv  = sm;                  // 16384 (64 KB)
    float* shBuf = shWv + 16384;        // 8 * 1024  per-warp Y staging
    float* shCb  = shBuf + 8192;        // 8 * 64    per-warp C

    const int tid  = threadIdx.x;
    const int lane = tid & 31;
    const int w    = tid >> 5;
    const unsigned FULL = 0xffffffffu;
    float* myL = shBuf + w * 1024;
    float* myC = shCb + w * WMAXD;

    for (int i = tid; i < D * D; i += 256) shWv[i] = Wv[i];
    __syncthreads();

    for (int n = blockIdx.x * 8 + w; n < N_NODES; n += gridDim.x * 8) {
        const int base = g_off[n];
        const int deg  = g_off[n + 1] - base;
        if (deg == 0) {
            ((float4*)g_h2)[(size_t)n * 32 + lane] = make_float4(0,0,0,0);
            continue;
        }

        float4 g4[H];
        #pragma unroll
        for (int h = 0; h < H; h++)
            g4[h] = ((const float4*)g_gk)[((size_t)n * H + h) * 32 + lane];

        float4 Y[H];
        #pragma unroll
        for (int h = 0; h < H; h++) Y[h] = make_float4(0,0,0,0);

        if (deg <= WMAXD) {
            for (int j = lane; j < deg; j += 32) myC[j] = g_C[base + j];
            __syncwarp();

            float s_own = 0.f;
            float4 qn = ((const float4*)g_q)[(size_t)base * 32 + lane];
            for (int i = 0; i < deg; i++) {
                const float4 q4 = qn;
                const float Ce = myC[i];
                if (i + 1 < deg)
                    qn = ((const float4*)g_q)[(size_t)(base + i + 1) * 32 + lane];
                float pr0 = q4.x*g4[0].x + q4.y*g4[0].y + q4.z*g4[0].z + q4.w*g4[0].w;
                float pr1 = q4.x*g4[1].x + q4.y*g4[1].y + q4.z*g4[1].z + q4.w*g4[1].w;
                float pr2 = q4.x*g4[2].x + q4.y*g4[2].y + q4.z*g4[2].z + q4.w*g4[2].w;
                float pr3 = q4.x*g4[3].x + q4.y*g4[3].y + q4.z*g4[3].z + q4.w*g4[3].w;
                float pr4 = q4.x*g4[4].x + q4.y*g4[4].y + q4.z*g4[4].z + q4.w*g4[4].w;
                float pr5 = q4.x*g4[5].x + q4.y*g4[5].y + q4.z*g4[5].z + q4.w*g4[5].w;
                float pr6 = q4.x*g4[6].x + q4.y*g4[6].y + q4.z*g4[6].z + q4.w*g4[6].w;
                float pr7 = q4.x*g4[7].x + q4.y*g4[7].y + q4.z*g4[7].z + q4.w*g4[7].w;
                #pragma unroll
                for (int off = 16; off >= 4; off >>= 1) {
                    pr0 += __shfl_xor_sync(FULL, pr0, off);
                    pr1 += __shfl_xor_sync(FULL, pr1, off);
                    pr2 += __shfl_xor_sync(FULL, pr2, off);
                    pr3 += __shfl_xor_sync(FULL, pr3, off);
                    pr4 += __shfl_xor_sync(FULL, pr4, off);
                    pr5 += __shfl_xor_sync(FULL, pr5, off);
                    pr6 += __shfl_xor_sync(FULL, pr6, off);
                    pr7 += __shfl_xor_sync(FULL, pr7, off);
                }
                const float t0 = (lane & 4) ? pr1 : pr0;
                const float t1 = (lane & 4) ? pr3 : pr2;
                const float t2 = (lane & 4) ? pr5 : pr4;
                const float t3 = (lane & 4) ? pr7 : pr6;
                const float u0 = (lane & 8) ? t1 : t0;
                const float u1 = (lane & 8) ? t3 : t2;
                float x = (lane & 16) ? u1 : u0;
                x += __shfl_xor_sync(FULL, x, 2);
                x += __shfl_xor_sync(FULL, x, 1);
                const float a = __expf(x * INV_SQRT_P) * Ce;
                s_own += a;
                const float a0 = __shfl_sync(FULL, a, 0);
                const float a1 = __shfl_sync(FULL, a, 4);
                const float a2 = __shfl_sync(FULL, a, 8);
                const float a3 = __shfl_sync(FULL, a, 12);
                const float a4 = __shfl_sync(FULL, a, 16);
                const float a5 = __shfl_sync(FULL, a, 20);
                const float a6 = __shfl_sync(FULL, a, 24);
                const float a7 = __shfl_sync(FULL, a, 28);
                Y[0].x += a0*q4.x; Y[0].y += a0*q4.y; Y[0].z += a0*q4.z; Y[0].w += a0*q4.w;
                Y[1].x += a1*q4.x; Y[1].y += a1*q4.y; Y[1].z += a1*q4.z; Y[1].w += a1*q4.w;
                Y[2].x += a2*q4.x; Y[2].y += a2*q4.y; Y[2].z += a2*q4.z; Y[2].w += a2*q4.w;
                Y[3].x += a3*q4.x; Y[3].y += a3*q4.y; Y[3].z += a3*q4.z; Y[3].w += a3*q4.w;
                Y[4].x += a4*q4.x; Y[4].y += a4*q4.y; Y[4].z += a4*q4.z; Y[4].w += a4*q4.w;
                Y[5].x += a5*q4.x; Y[5].y += a5*q4.y; Y[5].z += a5*q4.z; Y[5].w += a5*q4.w;
                Y[6].x += a6*q4.x; Y[6].y += a6*q4.y; Y[6].z += a6*q4.z; Y[6].w += a6*q4.w;
                Y[7].x += a7*q4.x; Y[7].y += a7*q4.y; Y[7].z += a7*q4.z; Y[7].w += a7*q4.w;
            }
            #pragma unroll
            for (int h = 0; h < H; h++) {
                const float sh_ = __shfl_sync(FULL, s_own, h << 2);
                const float si = 1.0f / sh_;
                Y[h].x *= si; Y[h].y *= si; Y[h].z *= si; Y[h].w *= si;
                *(float4*)&myL[h * D + lane * 4] = Y[h];
            }
            __syncwarp();
        } else {
            float m[H], s[H];
            #pragma unroll
            for (int h = 0; h < H; h++) { m[h] = -1e30f; s[h] = 0.f; }
            for (int i = 0; i < deg; i++) {
                const float4 q4 = ((const float4*)g_q)[(size_t)(base + i) * 32 + lane];
                const float Ce = g_C[base + i];
                #pragma unroll
                for (int h = 0; h < H; h++) {
                    float pq = q4.x*g4[h].x + q4.y*g4[h].y + q4.z*g4[h].z + q4.w*g4[h].w;
                    #pragma unroll
                    for (int o = 16; o; o >>= 1) pq += __shfl_xor_sync(FULL, pq, o);
                    pq *= INV_SQRT_P;
                    const float nm = fmaxf(m[h], pq);
                    const float sc = __expf(m[h] - nm);
                    const float ww = __expf(pq - nm) * Ce;
                    s[h] = s[h] * sc + ww;
                    Y[h].x = Y[h].x * sc + ww * q4.x;
                    Y[h].y = Y[h].y * sc + ww * q4.y;
                    Y[h].z = Y[h].z * sc + ww * q4.z;
                    Y[h].w = Y[h].w * sc + ww * q4.w;
                    m[h] = nm;
                }
            }
            #pragma unroll
            for (int h = 0; h < H; h++) {
                const float si = 1.0f / s[h];
                Y[h].x *= si; Y[h].y *= si; Y[h].z *= si; Y[h].w *= si;
                *(float4*)&myL[h * D + lane * 4] = Y[h];
            }
            __syncwarp();
        }

        // ---- epilogue: h2[j] = sum_d Y[j>>4, d] * Wv[d, j] ----
        const float* yrow = myL + (lane >> 2) * D;
        float4 hv = make_float4(0,0,0,0);
        #pragma unroll 8
        for (int d = 0; d < D; d += 4) {
            const float4 y4 = *(const float4*)&yrow[d];
            const float4 w0 = ((const float4*)shWv)[(d+0) * 32 + lane];
            const float4 w1 = ((const float4*)shWv)[(d+1) * 32 + lane];
            const float4 w2 = ((const float4*)shWv)[(d+2) * 32 + lane];
            const float4 w3 = ((const float4*)shWv)[(d+3) * 32 + lane];
            hv.x += y4.x*w0.x + y4.y*w1.x + y4.z*w2.x + y4.w*w3.x;
            hv.y += y4.x*w0.y + y4.y*w1.y + y4.z*w2.y + y4.w*w3.y;
            hv.z += y4.x*w0.z + y4.y*w1.z + y4.z*w2.z + y4.w*w3.z;
            hv.w += y4.x*w0.w + y4.y*w1.w + y4.z*w2.w + y4.w*w3.w;
        }
        ((float4*)g_h2)[(size_t)n * 32 + lane] = hv;
    }
}

// ---------------- K8: tiled m_agg = h2 @ Wo ----------------
__global__ void __launch_bounds__(256) k8_out(const float* __restrict__ Wo,
                                              float* __restrict__ outM) {
    extern __shared__ float sm[];
    float* shW = sm;             // 16384
    float* shq = shW + 16384;    // 4096
    const int tid = threadIdx.x;
    const int tx = tid & 31, ty = tid >> 5;

    for (int i = tid; i < D * D; i += 256) shW[i] = Wo[i];

    for (int tile = blockIdx.x; tile < N_NODES / 32; tile += gridDim.x) {
        const int n0 = tile * 32;
        __syncthreads();
        for (int i = tid; i < 1024; i += 256)
            ((float4*)shq)[i] = ((const float4*)g_h2)[(size_t)n0 * 32 + i];
        __syncthreads();

        float4 a0 = make_float4(0,0,0,0), a1 = a0, a2 = a0, a3 = a0;
        const float* q0 = shq + (ty * 4) * D;
        #pragma unroll 4
        for (int k = 0; k < D; k++) {
            const float4 wv = ((const float4*)shW)[k * 32 + tx];
            const float b0 = q0[k], b1 = q0[D + k], b2 = q0[2*D + k], b3 = q0[3*D + k];
            a0.x += b0*wv.x; a0.y += b0*wv.y; a0.z += b0*wv.z; a0.w += b0*wv.w;
            a1.x += b1*wv.x; a1.y += b1*wv.y; a1.z += b1*wv.z; a1.w += b1*wv.w;
            a2.x += b2*wv.x; a2.y += b2*wv.y; a2.z += b2*wv.z; a2.w += b2*wv.w;
            a3.x += b3*wv.x; a3.y += b3*wv.y; a3.z += b3*wv.z; a3.w += b3*wv.w;
        }
        ((float4*)outM)[(size_t)(n0 + ty*4 + 0) * 32 + tx] = a0;
        ((float4*)outM)[(size_t)(n0 + ty*4 + 1) * 32 + tx] = a1;
        ((float4*)outM)[(size_t)(n0 + ty*4 + 2) * 32 + tx] = a2;
        ((float4*)outM)[(size_t)(n0 + ty*4 + 3) * 32 + tx] = a3;
    }
}

// ---------------- launch ----------------
extern "C" void kernel_launch(void* const* d_in, const int* in_sizes, int n_in,
                              void* d_out, int out_size) {
    const float* pos  = (const float*)d_in[0];
    const float* h1   = (const float*)d_in[1];
    const float* t    = (const float*)d_in[2];
    const float* fw   = (const float*)d_in[3];
    const float* fb   = (const float*)d_in[4];
    const float* ln_g = (const float*)d_in[5];
    const float* ln_b = (const float*)d_in[6];
    const float* Wq   = (const float*)d_in[7];
    const float* Wk   = (const float*)d_in[8];
    const float* Wv   = (const float*)d_in[9];
    const float* Wo   = (const float*)d_in[10];
    const int* src    = (const int*)d_in[11];
    const int* dst    = (const int*)d_in[12];
    const int* q_id   = (const int*)d_in[13];

    float* out  = (float*)d_out;
    float* outM = out;                              // m_agg [N,D]
    float* outW = out + (size_t)N_NODES * D;        // W     [E,D]

    const size_t sm_k45 = (16384 + 16896 + 8192 + 8192) * sizeof(float) + 64 * sizeof(int);
    const size_t sm_k7  = (16384 + 8192 + 512) * sizeof(float);       // 100,352 B (2 CTAs/SM)
    const size_t sm_k8  = (16384 + 4096) * sizeof(float);

    cudaFuncSetAttribute(k45_gk,  cudaFuncAttributeMaxDynamicSharedMemorySize, (int)sm_k45);
    cudaFuncSetAttribute(k7_node, cudaFuncAttributeMaxDynamicSharedMemorySize, (int)sm_k7);
    cudaFuncSetAttribute(k8_out,  cudaFuncAttributeMaxDynamicSharedMemorySize, (int)sm_k8);

    kh_hist<<<256, 256>>>(src);                                       // 0
    k2_scan<<<1, 256>>>();                                            // 1
    k1_edge<<<N_EDGES / 128, 256>>>(pos, h1, t, fw, fb, ln_g, ln_b,
                                    src, dst, outW);                  // 2
    k45_gk<<<148, 512, sm_k45>>>(Wq, Wk, q_id);                       // 3  <-- profiled
    k7_node<<<296, 256, sm_k7>>>(Wv);                                 // 4
    k8_out<<<296, 256, sm_k8>>>(Wo, outM);                            // 5
}